// round 7
// baseline (speedup 1.0000x reference)
#include <cuda_runtime.h>
#include <cuda_bf16.h>
#include <cstdint>

// ---------------- problem constants ----------------
#define N_TOT 8192
#define D     128
#define IPC_C 512
#define ROW0  7680            // bz - IPC
#define NCOL  7680            // unmasked columns [0, 7680)
#define BM    128
#define BN    256
#define NTIL  (NCOL / BN)     // 30 column tiles
#define NGRP  (NCOL / 8)      // 960 8-column groups; groups [0,128) = easy
#define LDB   136             // bf16 smem row stride (units of bf16)
#define WINDW 0.009f          // rigorous bf16-vs-fp32 dot error window (2B + margin)

// ---------------- device globals ----------------
__device__ __nv_bfloat16 g_bf[N_TOT * D];     // normalized bf16
__device__ float g_inv[N_TOT];                // inverse norms
__device__ float g_sub[IPC_C * NGRP];         // per-(row, 8col-group) approx max
__device__ float g_bpart[16];                 // per-block loss partials
__device__ int   g_done;                      // zero-init; reset each replay

#define CP_ASYNC16(dst_u32, src_ptr) \
    asm volatile("cp.async.cg.shared.global [%0], [%1], 16;" \
                 :: "r"(dst_u32), "l"(src_ptr) : "memory")
#define CP_COMMIT()  asm volatile("cp.async.commit_group;" ::: "memory")
#define CP_WAIT0()   asm volatile("cp.async.wait_group 0;" ::: "memory")

// ---------------- kernel 1: normalize -> bf16 + inv norms ----------------
__global__ void __launch_bounds__(256) prep_kernel(const float* __restrict__ f) {
    int row  = blockIdx.x * 8 + (threadIdx.x >> 5);
    int lane = threadIdx.x & 31;
    float4 v = ((const float4*)(f + (size_t)row * D))[lane];
    float s = v.x * v.x + v.y * v.y + v.z * v.z + v.w * v.w;
    #pragma unroll
    for (int o = 16; o; o >>= 1) s += __shfl_xor_sync(0xffffffffu, s, o);
    float inv = rsqrtf(s);
    if (!(s > 1e-24f)) inv = 1e12f;
    if (lane == 0) g_inv[row] = inv;

    __nv_bfloat162 p0 = __floats2bfloat162_rn(v.x * inv, v.y * inv);
    __nv_bfloat162 p1 = __floats2bfloat162_rn(v.z * inv, v.w * inv);
    uint2 packed = make_uint2(*(uint32_t*)&p0, *(uint32_t*)&p1);
    *(uint2*)(g_bf + (size_t)row * D + lane * 4) = packed;
}

// ---------------- kernel 2: bf16 m16n8k16 GEMM + per-group max ----------------
// 512 threads = 16 warps (4m x 4n); warp tile 32x64.
// smem: A bf16[128][136] + B bf16[256][136] = 104448 B
#define SMEM_BYTES (BM * LDB * 2 + BN * LDB * 2)

__global__ void __launch_bounds__(512, 1) gemm_kernel() {
    extern __shared__ char smraw[];
    __nv_bfloat16* As = (__nv_bfloat16*)smraw;
    __nv_bfloat16* Bs = As + BM * LDB;

    const int tid  = threadIdx.x;
    const int lane = tid & 31;
    const int w    = tid >> 5;
    const int wm   = w >> 2;        // 0..3
    const int wn   = w & 3;         // 0..3
    const int q    = lane >> 2;     // 0..7
    const int tig  = lane & 3;      // 0..3
    const int rowBase = ROW0 + blockIdx.y * BM;
    const int colBase = blockIdx.x * BN;

    const uint32_t sA = (uint32_t)__cvta_generic_to_shared(As);
    const uint32_t sB = (uint32_t)__cvta_generic_to_shared(Bs);

    // stage A: 128 rows x 16 chunks of 16B
    #pragma unroll
    for (int t = 0; t < 4; t++) {
        int idx = tid + t * 512;
        int r = idx >> 4, c = idx & 15;
        CP_ASYNC16(sA + r * (LDB * 2) + c * 16,
                   g_bf + (size_t)(rowBase + r) * D + c * 8);
    }
    // stage B: 256 rows x 16 chunks
    #pragma unroll
    for (int t = 0; t < 8; t++) {
        int idx = tid + t * 512;
        int r = idx >> 4, c = idx & 15;
        CP_ASYNC16(sB + r * (LDB * 2) + c * 16,
                   g_bf + (size_t)(colBase + r) * D + c * 8);
    }
    CP_COMMIT();
    CP_WAIT0();
    __syncthreads();

    float acc[2][8][4];
    #pragma unroll
    for (int mt = 0; mt < 2; mt++)
        #pragma unroll
        for (int nt = 0; nt < 8; nt++)
            #pragma unroll
            for (int e = 0; e < 4; e++) acc[mt][nt][e] = 0.f;

    const uint32_t* A32 = (const uint32_t*)As;   // 4B units: row*68 + k/2
    const uint32_t* B32 = (const uint32_t*)Bs;
    const int rA0 = wm * 32 + q;
    const int rB0 = wn * 64 + q;

    #pragma unroll
    for (int s = 0; s < 8; s++) {            // 8 K-steps of k16
        const int ko = s * 8 + tig;
        uint32_t af[2][4];
        #pragma unroll
        for (int mt = 0; mt < 2; mt++) {
            int b0 = (rA0 + mt * 16) * 68 + ko;
            af[mt][0] = A32[b0];
            af[mt][1] = A32[b0 + 8 * 68];
            af[mt][2] = A32[b0 + 4];
            af[mt][3] = A32[b0 + 8 * 68 + 4];
        }
        uint32_t bf[8][2];
        #pragma unroll
        for (int nt = 0; nt < 8; nt++) {
            int b0 = (rB0 + nt * 8) * 68 + ko;
            bf[nt][0] = B32[b0];
            bf[nt][1] = B32[b0 + 4];
        }
        #pragma unroll
        for (int mt = 0; mt < 2; mt++)
            #pragma unroll
            for (int nt = 0; nt < 8; nt++)
                asm volatile(
                    "mma.sync.aligned.m16n8k16.row.col.f32.bf16.bf16.f32 "
                    "{%0,%1,%2,%3}, {%4,%5,%6,%7}, {%8,%9}, {%0,%1,%2,%3};"
                    : "+f"(acc[mt][nt][0]), "+f"(acc[mt][nt][1]),
                      "+f"(acc[mt][nt][2]), "+f"(acc[mt][nt][3])
                    : "r"(af[mt][0]), "r"(af[mt][1]), "r"(af[mt][2]), "r"(af[mt][3]),
                      "r"(bf[nt][0]), "r"(bf[nt][1]));
    }
    __syncthreads();   // all smem reads done before reuse

    // per-(row, 8col-group) maxima into smem pm[128][32]
    float* pm = (float*)smraw;
    #pragma unroll
    for (int mt = 0; mt < 2; mt++)
        #pragma unroll
        for (int nt = 0; nt < 8; nt++) {
            float vlo = fmaxf(acc[mt][nt][0], acc[mt][nt][1]);  // row q
            float vhi = fmaxf(acc[mt][nt][2], acc[mt][nt][3]);  // row q+8
            #pragma unroll
            for (int o = 1; o < 4; o <<= 1) {
                vlo = fmaxf(vlo, __shfl_xor_sync(0xffffffffu, vlo, o));
                vhi = fmaxf(vhi, __shfl_xor_sync(0xffffffffu, vhi, o));
            }
            if (tig == 0) {
                int g = wn * 8 + nt;
                int r = wm * 32 + mt * 16 + q;
                pm[r * 32 + g]       = vlo;
                pm[(r + 8) * 32 + g] = vhi;
            }
        }
    __syncthreads();

    // coalesced write: [row][group] global layout
    {
        int row = tid >> 2, g0 = (tid & 3) * 8;
        float4 x = *(float4*)(pm + row * 32 + g0);
        float4 y = *(float4*)(pm + row * 32 + g0 + 4);
        size_t dst = (size_t)(blockIdx.y * BM + row) * NGRP + blockIdx.x * 32 + g0;
        *(float4*)(g_sub + dst)     = x;
        *(float4*)(g_sub + dst + 4) = y;
    }
}

// ---------------- kernel 3: exact refine + loss ----------------
// 16 blocks x 1024 threads; warp per row (512 rows).
__global__ void __launch_bounds__(1024) refine_kernel(const float* __restrict__ fvec,
                                                      const float* __restrict__ a_scl,
                                                      float* __restrict__ out) {
    __shared__ float red[32];
    const int tid  = threadIdx.x;
    const int lane = tid & 31;
    const int wid  = tid >> 5;
    const int r    = blockIdx.x * 32 + wid;       // 0..511
    const float* sub = g_sub + (size_t)r * NGRP;

    // pass 1: approx class maxima (groups j<4*32=128 -> easy)
    float emax = -2.f, hmax = -2.f;
    #pragma unroll
    for (int j = 0; j < 30; j++) {
        float v = sub[lane + 32 * j];
        if (j < 4) emax = fmaxf(emax, v); else hmax = fmaxf(hmax, v);
    }
    #pragma unroll
    for (int o = 16; o; o >>= 1) {
        emax = fmaxf(emax, __shfl_xor_sync(0xffffffffu, emax, o));
        hmax = fmaxf(hmax, __shfl_xor_sync(0xffffffffu, hmax, o));
    }

    // pass 2: exact fp32 recompute of candidate groups
    const float inv_r = g_inv[ROW0 + r];
    const float4* R4 = (const float4*)(fvec + (size_t)(ROW0 + r) * D);
    float eEx = -2.f, hEx = -2.f;
    #pragma unroll 1
    for (int j = 0; j < 30; j++) {
        float v = sub[lane + 32 * j];
        bool easy = (j < 4);
        float thr = (easy ? emax : hmax) - WINDW;
        unsigned m = __ballot_sync(0xffffffffu, v >= thr);
        while (m) {
            int l = __ffs(m) - 1; m &= m - 1;
            int g = l + 32 * j;
            int c = g * 8 + (lane & 7);
            int seg = lane >> 3;
            const float4* C4 = (const float4*)(fvec + (size_t)c * D);
            float p = 0.f;
            #pragma unroll
            for (int t = 0; t < 8; t++) {
                float4 x = R4[seg * 8 + t];
                float4 y = C4[seg * 8 + t];
                p = fmaf(x.x, y.x, p); p = fmaf(x.y, y.y, p);
                p = fmaf(x.z, y.z, p); p = fmaf(x.w, y.w, p);
            }
            p += __shfl_xor_sync(0xffffffffu, p, 8);
            p += __shfl_xor_sync(0xffffffffu, p, 16);
            float d = p * inv_r * g_inv[c];
            #pragma unroll
            for (int o = 1; o < 8; o <<= 1)
                d = fmaxf(d, __shfl_xor_sync(0xffffffffu, d, o));
            if (easy) eEx = fmaxf(eEx, d); else hEx = fmaxf(hEx, d);
        }
    }

    if (lane == 0) red[wid] = log1pf(expf((hEx - eEx) * 10.0f));  // 1/SIGMA1 = 10
    __syncthreads();

    if (tid == 0) {
        float s = 0.f;
        #pragma unroll
        for (int i = 0; i < 32; i++) s += red[i];
        g_bpart[blockIdx.x] = s;
        __threadfence();
        if (atomicAdd(&g_done, 1) == 15) {
            __threadfence();
            float tot = 0.f;
            #pragma unroll
            for (int i = 0; i < 16; i++) tot += g_bpart[i];
            out[0] = a_scl[0] * tot * (1.0f / 512.0f);
            g_done = 0;
        }
    }
}

extern "C" void kernel_launch(void* const* d_in, const int* in_sizes, int n_in,
                              void* d_out, int out_size) {
    const float* fvec = (const float*)d_in[0];   // [8192,128] f32
    // d_in[1] = Lvec (dead in the reference math)
    const float* a    = (const float*)d_in[2];   // scalar f32
    float* out = (float*)d_out;

    cudaFuncSetAttribute(gemm_kernel,
                         cudaFuncAttributeMaxDynamicSharedMemorySize, SMEM_BYTES);

    prep_kernel<<<N_TOT / 8, 256>>>(fvec);
    gemm_kernel<<<dim3(NTIL, IPC_C / BM), 512, SMEM_BYTES>>>();
    refine_kernel<<<16, 1024>>>(fvec, a, out);
}

// round 8
// speedup vs baseline: 2.7518x; 2.7518x over previous
#include <cuda_runtime.h>
#include <cuda_bf16.h>
#include <cstdint>

// ---------------- problem constants ----------------
#define N_TOT 8192
#define D     128
#define IPC_C 512
#define ROW0  7680            // bz - IPC
#define NCOL  7680            // unmasked columns [0, 7680)
#define BM    128
#define BN    256
#define NTIL  (NCOL / BN)     // 30 column tiles
#define ETIL  (1024 / BN)     // tiles [0,4) = easy region (exact boundary)
#define NBLK  (NTIL * (IPC_C / BM))   // 120 blocks = one wave
#define LDB   136             // bf16 smem row stride (bf16 units); 68 uint32

// ---------------- device globals ----------------
__device__ __nv_bfloat16 g_bf[N_TOT * D];   // normalized bf16
__device__ float g_part[NTIL * IPC_C];      // [colTile][row] partial maxima
__device__ int   g_done;                    // zero-init; reset each replay

#define CP_ASYNC16(dst_u32, src_ptr) \
    asm volatile("cp.async.cg.shared.global [%0], [%1], 16;" \
                 :: "r"(dst_u32), "l"(src_ptr) : "memory")
#define CP_COMMIT()  asm volatile("cp.async.commit_group;" ::: "memory")
#define CP_WAIT0()   asm volatile("cp.async.wait_group 0;" ::: "memory")

// ---------------- kernel 1: normalize -> bf16 ----------------
__global__ void __launch_bounds__(256) prep_kernel(const float* __restrict__ f) {
    int row  = blockIdx.x * 8 + (threadIdx.x >> 5);
    int lane = threadIdx.x & 31;
    float4 v = ((const float4*)(f + (size_t)row * D))[lane];
    float s = v.x * v.x + v.y * v.y + v.z * v.z + v.w * v.w;
    #pragma unroll
    for (int o = 16; o; o >>= 1) s += __shfl_xor_sync(0xffffffffu, s, o);
    float inv = rsqrtf(s);
    if (!(s > 1e-24f)) inv = 1e12f;

    __nv_bfloat162 p0 = __floats2bfloat162_rn(v.x * inv, v.y * inv);
    __nv_bfloat162 p1 = __floats2bfloat162_rn(v.z * inv, v.w * inv);
    uint2 packed = make_uint2(*(uint32_t*)&p0, *(uint32_t*)&p1);
    *(uint2*)(g_bf + (size_t)row * D + lane * 4) = packed;
}

// ---------------- kernel 2: bf16 m16n8k16 GEMM + row-max + fused finalize ----------------
// 512 threads = 16 warps (4m x 4n); warp tile 32x64.
// smem: A bf16[128][136] + B bf16[256][136] = 104448 B
#define SMEM_BYTES (BM * LDB * 2 + BN * LDB * 2)

__global__ void __launch_bounds__(512, 1) gemm_kernel(const float* __restrict__ a_scl,
                                                      float* __restrict__ out) {
    extern __shared__ char smraw[];
    __nv_bfloat16* As = (__nv_bfloat16*)smraw;
    __nv_bfloat16* Bs = As + BM * LDB;

    const int tid  = threadIdx.x;
    const int lane = tid & 31;
    const int w    = tid >> 5;
    const int wm   = w >> 2;        // 0..3 -> 32-row strip
    const int wn   = w & 3;         // 0..3 -> 64-col strip
    const int q    = lane >> 2;     // 0..7
    const int tig  = lane & 3;      // 0..3
    const int rowBase = ROW0 + blockIdx.y * BM;
    const int colBase = blockIdx.x * BN;

    const uint32_t sA = (uint32_t)__cvta_generic_to_shared(As);
    const uint32_t sB = (uint32_t)__cvta_generic_to_shared(Bs);

    // ---- stage A (128 rows) and B (256 rows), 16 x 16B chunks per row ----
    #pragma unroll
    for (int t = 0; t < 4; t++) {
        int idx = tid + t * 512;
        int r = idx >> 4, c = idx & 15;
        CP_ASYNC16(sA + r * (LDB * 2) + c * 16,
                   g_bf + (size_t)(rowBase + r) * D + c * 8);
    }
    #pragma unroll
    for (int t = 0; t < 8; t++) {
        int idx = tid + t * 512;
        int r = idx >> 4, c = idx & 15;
        CP_ASYNC16(sB + r * (LDB * 2) + c * 16,
                   g_bf + (size_t)(colBase + r) * D + c * 8);
    }
    CP_COMMIT();
    CP_WAIT0();
    __syncthreads();

    float acc[2][8][4];
    #pragma unroll
    for (int mt = 0; mt < 2; mt++)
        #pragma unroll
        for (int nt = 0; nt < 8; nt++)
            #pragma unroll
            for (int e = 0; e < 4; e++) acc[mt][nt][e] = 0.f;

    const uint32_t* A32 = (const uint32_t*)As;   // row*68 + kpair
    const uint32_t* B32 = (const uint32_t*)Bs;
    const int rA0 = wm * 32 + q;
    const int rB0 = wn * 64 + q;

    #pragma unroll
    for (int s = 0; s < 8; s++) {            // 8 K-steps of k16
        const int ko = s * 8 + tig;
        uint32_t af[2][4];
        #pragma unroll
        for (int mt = 0; mt < 2; mt++) {
            int b0 = (rA0 + mt * 16) * 68 + ko;
            af[mt][0] = A32[b0];
            af[mt][1] = A32[b0 + 8 * 68];
            af[mt][2] = A32[b0 + 4];
            af[mt][3] = A32[b0 + 8 * 68 + 4];
        }
        uint32_t bf[8][2];
        #pragma unroll
        for (int nt = 0; nt < 8; nt++) {
            int b0 = (rB0 + nt * 8) * 68 + ko;
            bf[nt][0] = B32[b0];
            bf[nt][1] = B32[b0 + 4];
        }
        #pragma unroll
        for (int mt = 0; mt < 2; mt++)
            #pragma unroll
            for (int nt = 0; nt < 8; nt++)
                asm volatile(
                    "mma.sync.aligned.m16n8k16.row.col.f32.bf16.bf16.f32 "
                    "{%0,%1,%2,%3}, {%4,%5,%6,%7}, {%8,%9}, {%0,%1,%2,%3};"
                    : "+f"(acc[mt][nt][0]), "+f"(acc[mt][nt][1]),
                      "+f"(acc[mt][nt][2]), "+f"(acc[mt][nt][3])
                    : "r"(af[mt][0]), "r"(af[mt][1]), "r"(af[mt][2]), "r"(af[mt][3]),
                      "r"(bf[nt][0]), "r"(bf[nt][1]));
    }
    __syncthreads();   // all smem reads done before reuse

    // ---- row max: thread -> quad shfl -> cross-warp via smem ----
    float* pm = (float*)smraw;    // [4(wn)][128]
    #pragma unroll
    for (int mt = 0; mt < 2; mt++) {
        float mlo = -2.f, mhi = -2.f;
        #pragma unroll
        for (int nt = 0; nt < 8; nt++) {
            mlo = fmaxf(mlo, fmaxf(acc[mt][nt][0], acc[mt][nt][1]));
            mhi = fmaxf(mhi, fmaxf(acc[mt][nt][2], acc[mt][nt][3]));
        }
        #pragma unroll
        for (int o = 1; o < 4; o <<= 1) {
            mlo = fmaxf(mlo, __shfl_xor_sync(0xffffffffu, mlo, o));
            mhi = fmaxf(mhi, __shfl_xor_sync(0xffffffffu, mhi, o));
        }
        if (tig == 0) {
            int r = wm * 32 + mt * 16 + q;
            pm[wn * 128 + r]     = mlo;
            pm[wn * 128 + r + 8] = mhi;
        }
    }
    __syncthreads();

    if (tid < BM) {
        float m = fmaxf(fmaxf(pm[tid], pm[128 + tid]),
                        fmaxf(pm[256 + tid], pm[384 + tid]));
        g_part[blockIdx.x * IPC_C + blockIdx.y * BM + tid] = m;
    }
    __syncthreads();

    // ---- last-block-done fused finalize ----
    __shared__ int isLast;
    __shared__ float red[512];
    if (tid == 0) {
        __threadfence();
        isLast = (atomicAdd(&g_done, 1) == NBLK - 1);
    }
    __syncthreads();
    if (!isLast) return;
    if (tid == 0) __threadfence();
    __syncthreads();

    float e = -2.f, h = -2.f;
    #pragma unroll
    for (int j = 0; j < ETIL; j++)     e = fmaxf(e, g_part[j * IPC_C + tid]);
    #pragma unroll
    for (int j = ETIL; j < NTIL; j++)  h = fmaxf(h, g_part[j * IPC_C + tid]);
    red[tid] = log1pf(expf((h - e) * 10.0f));   // 1/SIGMA1 = 10
    __syncthreads();
    #pragma unroll
    for (int s2 = 256; s2; s2 >>= 1) {
        if (tid < s2) red[tid] += red[tid + s2];
        __syncthreads();
    }
    if (tid == 0) {
        out[0] = a_scl[0] * red[0] * (1.0f / 512.0f);
        g_done = 0;      // reset for the next graph replay
    }
}

extern "C" void kernel_launch(void* const* d_in, const int* in_sizes, int n_in,
                              void* d_out, int out_size) {
    const float* fvec = (const float*)d_in[0];   // [8192,128] f32
    // d_in[1] = Lvec (dead in the reference math)
    const float* a    = (const float*)d_in[2];   // scalar f32
    float* out = (float*)d_out;

    cudaFuncSetAttribute(gemm_kernel,
                         cudaFuncAttributeMaxDynamicSharedMemorySize, SMEM_BYTES);

    prep_kernel<<<N_TOT / 8, 256>>>(fvec);
    gemm_kernel<<<dim3(NTIL, IPC_C / BM), 512, SMEM_BYTES>>>(a, out);
}